// round 12
// baseline (speedup 1.0000x reference)
#include <cuda_runtime.h>
#include <cstdint>

#define CN0  400000
#define CN1  40000
#define CN2  4000
#define CIN  128
#define CHID 256
#define COUT 64
#define CE1  640000
#define CE2  64000
#define NB1  40
#define NB2  4
#define NBT  (NB1 + NB2)

// ---- scratch (device globals: no allocation allowed) ----
__device__ float g_agg1[CN1 * CIN];
__device__ float g_h   [CN1 * CHID];
__device__ int   g_cnt1[CN1];
__device__ int   g_off1[CN1 + 1];
__device__ int   g_csr1[CE1];
__device__ int   g_cnt2[CN2];
__device__ int   g_off2[CN2 + 1];
__device__ int   g_csr2[CE2];
__device__ int   g_bsum[64];
__device__ int   g_scan_done;

// ---------------------------------------------------------------------------
__global__ void k_zero() {
    int i = blockIdx.x * blockDim.x + threadIdx.x;
    if (i < CN1) g_cnt1[i] = 0;
    if (i < CN2) g_cnt2[i] = 0;
    if (i == 0) g_scan_done = 0;
}

// merged histogram, 4 edges/thread via int4 loads (MLP=4)
__global__ void k_count(const int* __restrict__ d1, const int* __restrict__ d2,
                        int E1, int E2) {
    int q = blockIdx.x * blockDim.x + threadIdx.x;
    int nq1 = E1 >> 2, nq2 = E2 >> 2;
    if (q < nq1) {
        int4 d = ((const int4*)d1)[q];
        atomicAdd(g_cnt1 + d.x, 1);
        atomicAdd(g_cnt1 + d.y, 1);
        atomicAdd(g_cnt1 + d.z, 1);
        atomicAdd(g_cnt1 + d.w, 1);
    } else if (q - nq1 < nq2) {
        int4 d = ((const int4*)d2)[q - nq1];
        atomicAdd(g_cnt2 + d.x, 1);
        atomicAdd(g_cnt2 + d.y, 1);
        atomicAdd(g_cnt2 + d.z, 1);
        atomicAdd(g_cnt2 + d.w, 1);
    } else if (q == nq1 + nq2) {                   // tails (E not multiple of 4)
        for (int i = nq1 * 4; i < E1; i++) atomicAdd(g_cnt1 + d1[i], 1);
        for (int i = nq2 * 4; i < E2; i++) atomicAdd(g_cnt2 + d2[i], 1);
    }
}

// ---------------------------------------------------------------------------
// Single-kernel segmented scan with device-wide spin barrier (44 blocks).
// ---------------------------------------------------------------------------
__global__ void __launch_bounds__(1024) k_scan(int E1, int E2) {
    int b = blockIdx.x;
    int lay = (b >= NB1);
    int bb = lay ? b - NB1 : b;
    int n = lay ? CN2 : CN1;
    int segbase = lay ? NB1 : 0;
    int* cnt = lay ? g_cnt2 : g_cnt1;
    int* off = lay ? g_off2 : g_off1;
    __shared__ int ps[1024];
    __shared__ int add_s;
    int t = threadIdx.x;
    int i = bb * 1024 + t;
    int v = (i < n) ? cnt[i] : 0;
    ps[t] = v;
    __syncthreads();
    #pragma unroll
    for (int d = 1; d < 1024; d <<= 1) {
        int u = (t >= d) ? ps[t - d] : 0;
        __syncthreads();
        ps[t] += u;
        __syncthreads();
    }
    int local_ex = ps[t] - v;
    if (t == 0) g_bsum[b] = ps[1023];
    __threadfence();
    __syncthreads();
    if (t == 0) {
        atomicAdd(&g_scan_done, 1);
        while (*(volatile int*)&g_scan_done < NBT) { }
        __threadfence();
        int s = 0;
        for (int j = segbase; j < b; j++) s += g_bsum[j];
        add_s = s;
    }
    __syncthreads();
    int add = add_s;
    if (i < n) { off[i] = local_ex + add; cnt[i] = 0; }
    if (i == 0) off[n] = lay ? E2 : E1;
}

// merged ticket fill, 4 edges/thread via int4 loads (4 parallel atomic chains)
__global__ void k_fill(const int* __restrict__ s1, const int* __restrict__ d1,
                       const int* __restrict__ s2, const int* __restrict__ d2,
                       int E1, int E2) {
    int q = blockIdx.x * blockDim.x + threadIdx.x;
    int nq1 = E1 >> 2, nq2 = E2 >> 2;
    if (q < nq1) {
        int4 d = ((const int4*)d1)[q];
        int4 s = ((const int4*)s1)[q];
        int p0 = atomicAdd(g_cnt1 + d.x, 1);
        int p1 = atomicAdd(g_cnt1 + d.y, 1);
        int p2 = atomicAdd(g_cnt1 + d.z, 1);
        int p3 = atomicAdd(g_cnt1 + d.w, 1);
        g_csr1[g_off1[d.x] + p0] = s.x;
        g_csr1[g_off1[d.y] + p1] = s.y;
        g_csr1[g_off1[d.z] + p2] = s.z;
        g_csr1[g_off1[d.w] + p3] = s.w;
    } else if (q - nq1 < nq2) {
        int j = q - nq1;
        int4 d = ((const int4*)d2)[j];
        int4 s = ((const int4*)s2)[j];
        int p0 = atomicAdd(g_cnt2 + d.x, 1);
        int p1 = atomicAdd(g_cnt2 + d.y, 1);
        int p2 = atomicAdd(g_cnt2 + d.z, 1);
        int p3 = atomicAdd(g_cnt2 + d.w, 1);
        g_csr2[g_off2[d.x] + p0] = s.x;
        g_csr2[g_off2[d.y] + p1] = s.y;
        g_csr2[g_off2[d.z] + p2] = s.z;
        g_csr2[g_off2[d.w] + p3] = s.w;
    } else if (q == nq1 + nq2) {                   // tails
        for (int i = nq1 * 4; i < E1; i++) {
            int d = d1[i];
            int p = atomicAdd(g_cnt1 + d, 1);
            g_csr1[g_off1[d] + p] = s1[i];
        }
        for (int i = nq2 * 4; i < E2; i++) {
            int d = d2[i];
            int p = atomicAdd(g_cnt2 + d, 1);
            g_csr2[g_off2[d] + p] = s2[i];
        }
    }
}

// ---------------------------------------------------------------------------
// layer-1 gather-mean: warp per dst row, unroll 8 (8 row-loads in flight/lane)
// ---------------------------------------------------------------------------
__global__ void __launch_bounds__(256) k_gather1(const float* __restrict__ x) {
    int w = (blockIdx.x * blockDim.x + threadIdx.x) >> 5;
    if (w >= CN1) return;
    int lane = threadIdx.x & 31;
    int e0 = g_off1[w], e1 = g_off1[w + 1];
    float4 acc = make_float4(0.f, 0.f, 0.f, 0.f);
    int i = e0;
    for (; i + 7 < e1; i += 8) {
        int sid[8];
        #pragma unroll
        for (int j = 0; j < 8; j++) sid[j] = g_csr1[i + j];
        float4 v[8];
        #pragma unroll
        for (int j = 0; j < 8; j++)
            v[j] = ((const float4*)(x + (size_t)sid[j] * CIN))[lane];
        #pragma unroll
        for (int j = 0; j < 8; j++) {
            acc.x += v[j].x; acc.y += v[j].y; acc.z += v[j].z; acc.w += v[j].w;
        }
    }
    for (; i + 3 < e1; i += 4) {
        int s0 = g_csr1[i], s1 = g_csr1[i + 1], s2 = g_csr1[i + 2], s3 = g_csr1[i + 3];
        float4 v0 = ((const float4*)(x + (size_t)s0 * CIN))[lane];
        float4 v1 = ((const float4*)(x + (size_t)s1 * CIN))[lane];
        float4 v2 = ((const float4*)(x + (size_t)s2 * CIN))[lane];
        float4 v3 = ((const float4*)(x + (size_t)s3 * CIN))[lane];
        acc.x += v0.x + v1.x + v2.x + v3.x;
        acc.y += v0.y + v1.y + v2.y + v3.y;
        acc.z += v0.z + v1.z + v2.z + v3.z;
        acc.w += v0.w + v1.w + v2.w + v3.w;
    }
    for (; i < e1; i++) {
        int s = g_csr1[i];
        float4 v = ((const float4*)(x + (size_t)s * CIN))[lane];
        acc.x += v.x; acc.y += v.y; acc.z += v.z; acc.w += v.w;
    }
    float id = 1.0f / fmaxf((float)(e1 - e0), 1.0f);
    acc.x *= id; acc.y *= id; acc.z *= id; acc.w *= id;
    ((float4*)(g_agg1 + (size_t)w * CIN))[lane] = acc;
}

// ---------------------------------------------------------------------------
// tf32 helpers — raw fp32 bits fed to mma.tf32 (HW truncates)
// ---------------------------------------------------------------------------
__device__ __forceinline__ void mma_tf32(float* c, const uint32_t* a, const uint32_t* b) {
    asm volatile(
        "mma.sync.aligned.m16n8k8.row.col.f32.tf32.tf32.f32 "
        "{%0,%1,%2,%3}, {%4,%5,%6,%7}, {%8,%9}, {%0,%1,%2,%3};"
        : "+f"(c[0]), "+f"(c[1]), "+f"(c[2]), "+f"(c[3])
        : "r"(a[0]), "r"(a[1]), "r"(a[2]), "r"(a[3]), "r"(b[0]), "r"(b[1]));
}

__device__ __forceinline__ uint32_t s2u(const void* p) {
    return (uint32_t)__cvta_generic_to_shared(p);
}

__device__ __forceinline__ void cp16(uint32_t dst, const void* src) {
    asm volatile("cp.async.cg.shared.global [%0], [%1], 16;"
                 :: "r"(dst), "l"(src));
}

// ---------------------------------------------------------------------------
// layer-1 GEMM (tf32, 3-stage cp.async pipeline, BM=64 x BN=256)
// ---------------------------------------------------------------------------
#define A_ST 1280
#define B_ST 4224
#define SMEM_GEMM1 ((3 * (A_ST + B_ST)) * 4)

__global__ void __launch_bounds__(256, 2) k_gemm1(const float* __restrict__ x,
                                                  const float* __restrict__ wl,
                                                  const float* __restrict__ wr,
                                                  const float* __restrict__ bias) {
    extern __shared__ float sm[];
    float* Abuf = sm;
    float* Bbuf = sm + 3 * A_ST;

    const int t = threadIdx.x;
    const int lane = t & 31, warp = t >> 5;
    const int warp_m = warp & 1;
    const int warp_n = warp >> 1;
    const int m0 = blockIdx.x * 64;
    const int fr = lane >> 2;
    const int fc = lane & 3;

    const int a_row = t >> 2,  a_kq = (t & 3) * 4;
    const int b_nq  = (t & 63) * 4;

    float acc[2][8][4] = {};

    auto issue = [&](int it, int st) {
        const int kk = (it & 7) * 16;
        const float* Abase = (it < 8) ? g_agg1 : x;
        const float* Bbase = (it < 8) ? wl : wr;
        float* As = Abuf + st * A_ST;
        float* Bs = Bbuf + st * B_ST;
        cp16(s2u(As + a_row * 20 + a_kq),
             Abase + (size_t)(m0 + a_row) * CIN + kk + a_kq);
        #pragma unroll
        for (int i = 0; i < 4; i++) {
            int krow = (t + i * 256) >> 6;
            cp16(s2u(Bs + krow * 264 + b_nq),
                 Bbase + (size_t)(kk + krow) * CHID + b_nq);
        }
    };

    issue(0, 0);
    asm volatile("cp.async.commit_group;");
    issue(1, 1);
    asm volatile("cp.async.commit_group;");

    int st = 0;
    for (int it = 0; it < 16; ++it) {
        asm volatile("cp.async.wait_group 1;");
        __syncthreads();
        if (it + 2 < 16) issue(it + 2, (st + 2) % 3);
        asm volatile("cp.async.commit_group;");

        const uint32_t* A = (const uint32_t*)(Abuf + st * A_ST);
        const uint32_t* B = (const uint32_t*)(Bbuf + st * B_ST);
        #pragma unroll
        for (int ks = 0; ks < 2; ks++) {
            const int kb = ks * 8;
            uint32_t a[2][4], b[8][2];
            #pragma unroll
            for (int mt = 0; mt < 2; mt++) {
                int mr = warp_m * 32 + mt * 16 + fr;
                a[mt][0] = A[mr * 20 + kb + fc];
                a[mt][1] = A[(mr + 8) * 20 + kb + fc];
                a[mt][2] = A[mr * 20 + kb + fc + 4];
                a[mt][3] = A[(mr + 8) * 20 + kb + fc + 4];
            }
            #pragma unroll
            for (int nt = 0; nt < 8; nt++) {
                int nc = warp_n * 64 + nt * 8 + fr;
                b[nt][0] = B[(kb + fc) * 264 + nc];
                b[nt][1] = B[(kb + fc + 4) * 264 + nc];
            }
            #pragma unroll
            for (int mt = 0; mt < 2; mt++)
                #pragma unroll
                for (int nt = 0; nt < 8; nt++)
                    mma_tf32(acc[mt][nt], a[mt], b[nt]);
        }
        st = (st + 1) % 3;
    }

    #pragma unroll
    for (int mt = 0; mt < 2; mt++) {
        int gm = m0 + warp_m * 32 + mt * 16 + fr;
        #pragma unroll
        for (int nt = 0; nt < 8; nt++) {
            int gn = warp_n * 64 + nt * 8 + (fc << 1);
            float b0 = bias[gn], b1 = bias[gn + 1];
            float2 v0 = make_float2(fmaxf(acc[mt][nt][0] + b0, 0.f),
                                    fmaxf(acc[mt][nt][1] + b1, 0.f));
            *(float2*)(g_h + (size_t)gm * CHID + gn) = v0;
            float2 v1 = make_float2(fmaxf(acc[mt][nt][2] + b0, 0.f),
                                    fmaxf(acc[mt][nt][3] + b1, 0.f));
            *(float2*)(g_h + (size_t)(gm + 8) * CHID + gn) = v1;
        }
    }
}

// ---------------------------------------------------------------------------
// FUSED layer-2: gather-mean + GEMM + log_softmax. Warp per dst row.
// ---------------------------------------------------------------------------
__global__ void __launch_bounds__(256) k_gemm2(const float* __restrict__ wl,
                                               const float* __restrict__ wr,
                                               const float* __restrict__ bias,
                                               float* __restrict__ out) {
    __shared__ float As[8][512];
    int warp = threadIdx.x >> 5, lane = threadIdx.x & 31;
    int m = blockIdx.x * 8 + warp;
    if (m >= CN2) return;

    {
        int e0 = g_off2[m], e1 = g_off2[m + 1];
        float4 a0 = make_float4(0.f, 0.f, 0.f, 0.f);
        float4 a1 = a0;
        int i = e0;
        for (; i + 1 < e1; i += 2) {
            const float4* p0 = (const float4*)(g_h + (size_t)g_csr2[i] * CHID);
            const float4* p1 = (const float4*)(g_h + (size_t)g_csr2[i + 1] * CHID);
            float4 u0 = p0[lane], u1 = p0[lane + 32];
            float4 v0 = p1[lane], v1 = p1[lane + 32];
            a0.x += u0.x + v0.x; a0.y += u0.y + v0.y;
            a0.z += u0.z + v0.z; a0.w += u0.w + v0.w;
            a1.x += u1.x + v1.x; a1.y += u1.y + v1.y;
            a1.z += u1.z + v1.z; a1.w += u1.w + v1.w;
        }
        for (; i < e1; i++) {
            const float4* p = (const float4*)(g_h + (size_t)g_csr2[i] * CHID);
            float4 u0 = p[lane], u1 = p[lane + 32];
            a0.x += u0.x; a0.y += u0.y; a0.z += u0.z; a0.w += u0.w;
            a1.x += u1.x; a1.y += u1.y; a1.z += u1.z; a1.w += u1.w;
        }
        float id = 1.0f / fmaxf((float)(e1 - e0), 1.0f);
        a0.x *= id; a0.y *= id; a0.z *= id; a0.w *= id;
        a1.x *= id; a1.y *= id; a1.z *= id; a1.w *= id;
        ((float4*)As[warp])[lane] = a0;
        ((float4*)As[warp])[lane + 32] = a1;
    }
    #pragma unroll
    for (int i = 0; i < 8; i++)
        As[warp][CHID + lane + 32 * i] = g_h[(size_t)m * CHID + lane + 32 * i];
    __syncwarp();

    float acc0 = 0.f, acc1 = 0.f;
    const float* A = As[warp];
    #pragma unroll 8
    for (int k = 0; k < CHID; k++) {
        float a = A[k];
        acc0 += a * wl[k * COUT + lane];
        acc1 += a * wl[k * COUT + lane + 32];
    }
    #pragma unroll 8
    for (int k = 0; k < CHID; k++) {
        float a = A[CHID + k];
        acc0 += a * wr[k * COUT + lane];
        acc1 += a * wr[k * COUT + lane + 32];
    }
    acc0 += bias[lane];
    acc1 += bias[lane + 32];

    float mx = fmaxf(acc0, acc1);
    #pragma unroll
    for (int o = 16; o > 0; o >>= 1) mx = fmaxf(mx, __shfl_xor_sync(0xFFFFFFFFu, mx, o));
    float s = expf(acc0 - mx) + expf(acc1 - mx);
    #pragma unroll
    for (int o = 16; o > 0; o >>= 1) s += __shfl_xor_sync(0xFFFFFFFFu, s, o);
    float lse = mx + logf(s);
    out[(size_t)m * COUT + lane]      = acc0 - lse;
    out[(size_t)m * COUT + lane + 32] = acc1 - lse;
}

// ---------------------------------------------------------------------------
extern "C" void kernel_launch(void* const* d_in, const int* in_sizes, int n_in,
                              void* d_out, int out_size) {
    const float* x    = (const float*)d_in[0];
    const int*   src1 = (const int*)d_in[1];
    const int*   dst1 = (const int*)d_in[2];
    const int*   src2 = (const int*)d_in[3];
    const int*   dst2 = (const int*)d_in[4];
    const float* wl1  = (const float*)d_in[5];
    const float* bl1  = (const float*)d_in[6];
    const float* wr1  = (const float*)d_in[7];
    const float* wl2  = (const float*)d_in[8];
    const float* bl2  = (const float*)d_in[9];
    const float* wr2  = (const float*)d_in[10];
    int E1 = in_sizes[1];
    int E2 = in_sizes[3];
    int nq = (E1 >> 2) + (E2 >> 2) + 1;

    cudaFuncSetAttribute(k_gemm1, cudaFuncAttributeMaxDynamicSharedMemorySize,
                         SMEM_GEMM1);

    k_zero<<<(CN1 + 1023) / 1024, 1024>>>();
    k_count<<<(nq + 255) / 256, 256>>>(dst1, dst2, E1, E2);
    k_scan<<<NBT, 1024>>>(E1, E2);
    k_fill<<<(nq + 255) / 256, 256>>>(src1, dst1, src2, dst2, E1, E2);
    k_gather1<<<(CN1 * 32 + 255) / 256, 256>>>(x);
    k_gemm1<<<CN1 / 64, 256, SMEM_GEMM1>>>(x, wl1, wr1, bl1);
    k_gemm2<<<(CN2 + 7) / 8, 256>>>(wl2, wr2, bl2, (float*)d_out);
}

// round 13
// speedup vs baseline: 1.0158x; 1.0158x over previous
#include <cuda_runtime.h>
#include <cstdint>

#define CN0  400000
#define CN1  40000
#define CN2  4000
#define CIN  128
#define CHID 256
#define COUT 64
#define CE1  640000
#define CE2  64000
#define NB1  40
#define NB2  4
#define NBT  (NB1 + NB2)

// ---- scratch (device globals: no allocation allowed) ----
__device__ float g_agg1[CN1 * CIN];
__device__ float g_h   [CN1 * CHID];
__device__ int   g_cnt1[CN1];
__device__ int   g_off1[CN1 + 1];
__device__ int   g_csr1[CE1];
__device__ int   g_pos1[CE1];
__device__ int   g_cnt2[CN2];
__device__ int   g_off2[CN2 + 1];
__device__ int   g_csr2[CE2];
__device__ int   g_pos2[CE2];
__device__ int   g_bsum[64];
__device__ int   g_scan_done;

// ---------------------------------------------------------------------------
__global__ void k_zero() {
    int i = blockIdx.x * blockDim.x + threadIdx.x;
    if (i < CN1) g_cnt1[i] = 0;
    if (i < CN2) g_cnt2[i] = 0;
    if (i == 0) g_scan_done = 0;
}

// merged histogram + ticket assignment (one edge/thread; ticket saved so the
// fill pass needs NO atomics)
__global__ void k_count(const int* __restrict__ d1, const int* __restrict__ d2,
                        int E1, int E2) {
    int i = blockIdx.x * blockDim.x + threadIdx.x;
    if (i < E1) {
        g_pos1[i] = atomicAdd(g_cnt1 + d1[i], 1);
    } else {
        int j = i - E1;
        if (j < E2) g_pos2[j] = atomicAdd(g_cnt2 + d2[j], 1);
    }
}

// ---------------------------------------------------------------------------
// Single-kernel segmented scan with device-wide spin barrier (44 blocks).
// ---------------------------------------------------------------------------
__global__ void __launch_bounds__(1024) k_scan(int E1, int E2) {
    int b = blockIdx.x;
    int lay = (b >= NB1);
    int bb = lay ? b - NB1 : b;
    int n = lay ? CN2 : CN1;
    int segbase = lay ? NB1 : 0;
    int* cnt = lay ? g_cnt2 : g_cnt1;
    int* off = lay ? g_off2 : g_off1;
    __shared__ int ps[1024];
    __shared__ int add_s;
    int t = threadIdx.x;
    int i = bb * 1024 + t;
    int v = (i < n) ? cnt[i] : 0;
    ps[t] = v;
    __syncthreads();
    #pragma unroll
    for (int d = 1; d < 1024; d <<= 1) {
        int u = (t >= d) ? ps[t - d] : 0;
        __syncthreads();
        ps[t] += u;
        __syncthreads();
    }
    int local_ex = ps[t] - v;
    if (t == 0) g_bsum[b] = ps[1023];
    __threadfence();
    __syncthreads();
    if (t == 0) {
        atomicAdd(&g_scan_done, 1);
        while (*(volatile int*)&g_scan_done < NBT) { }
        __threadfence();
        int s = 0;
        for (int j = segbase; j < b; j++) s += g_bsum[j];
        add_s = s;
    }
    __syncthreads();
    int add = add_s;
    if (i < n) off[i] = local_ex + add;
    if (i == 0) off[n] = lay ? E2 : E1;
}

// atomic-free fill: position precomputed in k_count
__global__ void k_fill(const int* __restrict__ s1, const int* __restrict__ d1,
                       const int* __restrict__ s2, const int* __restrict__ d2,
                       int E1, int E2) {
    int i = blockIdx.x * blockDim.x + threadIdx.x;
    if (i < E1) {
        int d = d1[i];
        g_csr1[g_off1[d] + g_pos1[i]] = s1[i];
    } else {
        int j = i - E1;
        if (j < E2) {
            int d = d2[j];
            g_csr2[g_off2[d] + g_pos2[j]] = s2[j];
        }
    }
}

// ---------------------------------------------------------------------------
// layer-1 gather-mean: warp per dst row, unroll 8
// ---------------------------------------------------------------------------
__global__ void __launch_bounds__(256) k_gather1(const float* __restrict__ x) {
    int w = (blockIdx.x * blockDim.x + threadIdx.x) >> 5;
    if (w >= CN1) return;
    int lane = threadIdx.x & 31;
    int e0 = g_off1[w], e1 = g_off1[w + 1];
    float4 acc = make_float4(0.f, 0.f, 0.f, 0.f);
    int i = e0;
    for (; i + 7 < e1; i += 8) {
        int sid[8];
        #pragma unroll
        for (int j = 0; j < 8; j++) sid[j] = g_csr1[i + j];
        float4 v[8];
        #pragma unroll
        for (int j = 0; j < 8; j++)
            v[j] = ((const float4*)(x + (size_t)sid[j] * CIN))[lane];
        #pragma unroll
        for (int j = 0; j < 8; j++) {
            acc.x += v[j].x; acc.y += v[j].y; acc.z += v[j].z; acc.w += v[j].w;
        }
    }
    for (; i + 3 < e1; i += 4) {
        int s0 = g_csr1[i], s1 = g_csr1[i + 1], s2 = g_csr1[i + 2], s3 = g_csr1[i + 3];
        float4 v0 = ((const float4*)(x + (size_t)s0 * CIN))[lane];
        float4 v1 = ((const float4*)(x + (size_t)s1 * CIN))[lane];
        float4 v2 = ((const float4*)(x + (size_t)s2 * CIN))[lane];
        float4 v3 = ((const float4*)(x + (size_t)s3 * CIN))[lane];
        acc.x += v0.x + v1.x + v2.x + v3.x;
        acc.y += v0.y + v1.y + v2.y + v3.y;
        acc.z += v0.z + v1.z + v2.z + v3.z;
        acc.w += v0.w + v1.w + v2.w + v3.w;
    }
    for (; i < e1; i++) {
        int s = g_csr1[i];
        float4 v = ((const float4*)(x + (size_t)s * CIN))[lane];
        acc.x += v.x; acc.y += v.y; acc.z += v.z; acc.w += v.w;
    }
    float id = 1.0f / fmaxf((float)(e1 - e0), 1.0f);
    acc.x *= id; acc.y *= id; acc.z *= id; acc.w *= id;
    ((float4*)(g_agg1 + (size_t)w * CIN))[lane] = acc;
}

// ---------------------------------------------------------------------------
// tf32 helpers — raw fp32 bits fed to mma.tf32 (HW truncates)
// ---------------------------------------------------------------------------
__device__ __forceinline__ void mma_tf32(float* c, const uint32_t* a, const uint32_t* b) {
    asm volatile(
        "mma.sync.aligned.m16n8k8.row.col.f32.tf32.tf32.f32 "
        "{%0,%1,%2,%3}, {%4,%5,%6,%7}, {%8,%9}, {%0,%1,%2,%3};"
        : "+f"(c[0]), "+f"(c[1]), "+f"(c[2]), "+f"(c[3])
        : "r"(a[0]), "r"(a[1]), "r"(a[2]), "r"(a[3]), "r"(b[0]), "r"(b[1]));
}

__device__ __forceinline__ uint32_t s2u(const void* p) {
    return (uint32_t)__cvta_generic_to_shared(p);
}

__device__ __forceinline__ void cp16(uint32_t dst, const void* src) {
    asm volatile("cp.async.cg.shared.global [%0], [%1], 16;"
                 :: "r"(dst), "l"(src));
}

// ---------------------------------------------------------------------------
// layer-1 GEMM (tf32, 3-stage cp.async pipeline, BM=64 x BN=256)
// ---------------------------------------------------------------------------
#define A_ST 1280
#define B_ST 4224
#define SMEM_GEMM1 ((3 * (A_ST + B_ST)) * 4)

__global__ void __launch_bounds__(256, 2) k_gemm1(const float* __restrict__ x,
                                                  const float* __restrict__ wl,
                                                  const float* __restrict__ wr,
                                                  const float* __restrict__ bias) {
    extern __shared__ float sm[];
    float* Abuf = sm;
    float* Bbuf = sm + 3 * A_ST;

    const int t = threadIdx.x;
    const int lane = t & 31, warp = t >> 5;
    const int warp_m = warp & 1;
    const int warp_n = warp >> 1;
    const int m0 = blockIdx.x * 64;
    const int fr = lane >> 2;
    const int fc = lane & 3;

    const int a_row = t >> 2,  a_kq = (t & 3) * 4;
    const int b_nq  = (t & 63) * 4;

    float acc[2][8][4] = {};

    auto issue = [&](int it, int st) {
        const int kk = (it & 7) * 16;
        const float* Abase = (it < 8) ? g_agg1 : x;
        const float* Bbase = (it < 8) ? wl : wr;
        float* As = Abuf + st * A_ST;
        float* Bs = Bbuf + st * B_ST;
        cp16(s2u(As + a_row * 20 + a_kq),
             Abase + (size_t)(m0 + a_row) * CIN + kk + a_kq);
        #pragma unroll
        for (int i = 0; i < 4; i++) {
            int krow = (t + i * 256) >> 6;
            cp16(s2u(Bs + krow * 264 + b_nq),
                 Bbase + (size_t)(kk + krow) * CHID + b_nq);
        }
    };

    issue(0, 0);
    asm volatile("cp.async.commit_group;");
    issue(1, 1);
    asm volatile("cp.async.commit_group;");

    int st = 0;
    for (int it = 0; it < 16; ++it) {
        asm volatile("cp.async.wait_group 1;");
        __syncthreads();
        if (it + 2 < 16) issue(it + 2, (st + 2) % 3);
        asm volatile("cp.async.commit_group;");

        const uint32_t* A = (const uint32_t*)(Abuf + st * A_ST);
        const uint32_t* B = (const uint32_t*)(Bbuf + st * B_ST);
        #pragma unroll
        for (int ks = 0; ks < 2; ks++) {
            const int kb = ks * 8;
            uint32_t a[2][4], b[8][2];
            #pragma unroll
            for (int mt = 0; mt < 2; mt++) {
                int mr = warp_m * 32 + mt * 16 + fr;
                a[mt][0] = A[mr * 20 + kb + fc];
                a[mt][1] = A[(mr + 8) * 20 + kb + fc];
                a[mt][2] = A[mr * 20 + kb + fc + 4];
                a[mt][3] = A[(mr + 8) * 20 + kb + fc + 4];
            }
            #pragma unroll
            for (int nt = 0; nt < 8; nt++) {
                int nc = warp_n * 64 + nt * 8 + fr;
                b[nt][0] = B[(kb + fc) * 264 + nc];
                b[nt][1] = B[(kb + fc + 4) * 264 + nc];
            }
            #pragma unroll
            for (int mt = 0; mt < 2; mt++)
                #pragma unroll
                for (int nt = 0; nt < 8; nt++)
                    mma_tf32(acc[mt][nt], a[mt], b[nt]);
        }
        st = (st + 1) % 3;
    }

    #pragma unroll
    for (int mt = 0; mt < 2; mt++) {
        int gm = m0 + warp_m * 32 + mt * 16 + fr;
        #pragma unroll
        for (int nt = 0; nt < 8; nt++) {
            int gn = warp_n * 64 + nt * 8 + (fc << 1);
            float b0 = bias[gn], b1 = bias[gn + 1];
            float2 v0 = make_float2(fmaxf(acc[mt][nt][0] + b0, 0.f),
                                    fmaxf(acc[mt][nt][1] + b1, 0.f));
            *(float2*)(g_h + (size_t)gm * CHID + gn) = v0;
            float2 v1 = make_float2(fmaxf(acc[mt][nt][2] + b0, 0.f),
                                    fmaxf(acc[mt][nt][3] + b1, 0.f));
            *(float2*)(g_h + (size_t)(gm + 8) * CHID + gn) = v1;
        }
    }
}

// ---------------------------------------------------------------------------
// FUSED layer-2: gather-mean + GEMM + log_softmax. Warp per dst row.
// ---------------------------------------------------------------------------
__global__ void __launch_bounds__(256) k_gemm2(const float* __restrict__ wl,
                                               const float* __restrict__ wr,
                                               const float* __restrict__ bias,
                                               float* __restrict__ out) {
    __shared__ float As[8][512];
    int warp = threadIdx.x >> 5, lane = threadIdx.x & 31;
    int m = blockIdx.x * 8 + warp;
    if (m >= CN2) return;

    {
        int e0 = g_off2[m], e1 = g_off2[m + 1];
        float4 a0 = make_float4(0.f, 0.f, 0.f, 0.f);
        float4 a1 = a0;
        int i = e0;
        for (; i + 1 < e1; i += 2) {
            const float4* p0 = (const float4*)(g_h + (size_t)g_csr2[i] * CHID);
            const float4* p1 = (const float4*)(g_h + (size_t)g_csr2[i + 1] * CHID);
            float4 u0 = p0[lane], u1 = p0[lane + 32];
            float4 v0 = p1[lane], v1 = p1[lane + 32];
            a0.x += u0.x + v0.x; a0.y += u0.y + v0.y;
            a0.z += u0.z + v0.z; a0.w += u0.w + v0.w;
            a1.x += u1.x + v1.x; a1.y += u1.y + v1.y;
            a1.z += u1.z + v1.z; a1.w += u1.w + v1.w;
        }
        for (; i < e1; i++) {
            const float4* p = (const float4*)(g_h + (size_t)g_csr2[i] * CHID);
            float4 u0 = p[lane], u1 = p[lane + 32];
            a0.x += u0.x; a0.y += u0.y; a0.z += u0.z; a0.w += u0.w;
            a1.x += u1.x; a1.y += u1.y; a1.z += u1.z; a1.w += u1.w;
        }
        float id = 1.0f / fmaxf((float)(e1 - e0), 1.0f);
        a0.x *= id; a0.y *= id; a0.z *= id; a0.w *= id;
        a1.x *= id; a1.y *= id; a1.z *= id; a1.w *= id;
        ((float4*)As[warp])[lane] = a0;
        ((float4*)As[warp])[lane + 32] = a1;
    }
    #pragma unroll
    for (int i = 0; i < 8; i++)
        As[warp][CHID + lane + 32 * i] = g_h[(size_t)m * CHID + lane + 32 * i];
    __syncwarp();

    float acc0 = 0.f, acc1 = 0.f;
    const float* A = As[warp];
    #pragma unroll 8
    for (int k = 0; k < CHID; k++) {
        float a = A[k];
        acc0 += a * wl[k * COUT + lane];
        acc1 += a * wl[k * COUT + lane + 32];
    }
    #pragma unroll 8
    for (int k = 0; k < CHID; k++) {
        float a = A[CHID + k];
        acc0 += a * wr[k * COUT + lane];
        acc1 += a * wr[k * COUT + lane + 32];
    }
    acc0 += bias[lane];
    acc1 += bias[lane + 32];

    float mx = fmaxf(acc0, acc1);
    #pragma unroll
    for (int o = 16; o > 0; o >>= 1) mx = fmaxf(mx, __shfl_xor_sync(0xFFFFFFFFu, mx, o));
    float s = expf(acc0 - mx) + expf(acc1 - mx);
    #pragma unroll
    for (int o = 16; o > 0; o >>= 1) s += __shfl_xor_sync(0xFFFFFFFFu, s, o);
    float lse = mx + logf(s);
    out[(size_t)m * COUT + lane]      = acc0 - lse;
    out[(size_t)m * COUT + lane + 32] = acc1 - lse;
}

// ---------------------------------------------------------------------------
extern "C" void kernel_launch(void* const* d_in, const int* in_sizes, int n_in,
                              void* d_out, int out_size) {
    const float* x    = (const float*)d_in[0];
    const int*   src1 = (const int*)d_in[1];
    const int*   dst1 = (const int*)d_in[2];
    const int*   src2 = (const int*)d_in[3];
    const int*   dst2 = (const int*)d_in[4];
    const float* wl1  = (const float*)d_in[5];
    const float* bl1  = (const float*)d_in[6];
    const float* wr1  = (const float*)d_in[7];
    const float* wl2  = (const float*)d_in[8];
    const float* bl2  = (const float*)d_in[9];
    const float* wr2  = (const float*)d_in[10];
    int E1 = in_sizes[1];
    int E2 = in_sizes[3];

    cudaFuncSetAttribute(k_gemm1, cudaFuncAttributeMaxDynamicSharedMemorySize,
                         SMEM_GEMM1);

    k_zero<<<(CN1 + 1023) / 1024, 1024>>>();
    k_count<<<(E1 + E2 + 255) / 256, 256>>>(dst1, dst2, E1, E2);
    k_scan<<<NBT, 1024>>>(E1, E2);
    k_fill<<<(E1 + E2 + 255) / 256, 256>>>(src1, dst1, src2, dst2, E1, E2);
    k_gather1<<<(CN1 * 32 + 255) / 256, 256>>>(x);
    k_gemm1<<<CN1 / 64, 256, SMEM_GEMM1>>>(x, wl1, wr1, bl1);
    k_gemm2<<<(CN2 + 7) / 8, 256>>>(wl2, wr2, bl2, (float*)d_out);
}

// round 14
// speedup vs baseline: 1.0246x; 1.0086x over previous
#include <cuda_runtime.h>
#include <cstdint>

#define CN0  400000
#define CN1  40000
#define CN2  4000
#define CIN  128
#define CHID 256
#define COUT 64
#define CE1  640000
#define CE2  64000
#define NB1  40
#define NB2  4
#define NBT  (NB1 + NB2)

// ---- scratch (device globals: zero-initialized at load; the graph is
//      self-cleaning: scan re-zeroes cnt, fill re-zeroes scan_done) ----
__device__ float g_agg1[CN1 * CIN];
__device__ float g_h   [CN1 * CHID];
__device__ int   g_cnt1[CN1];
__device__ int   g_off1[CN1 + 1];
__device__ int   g_csr1[CE1];
__device__ int   g_pos1[CE1];
__device__ int   g_cnt2[CN2];
__device__ int   g_off2[CN2 + 1];
__device__ int   g_csr2[CE2];
__device__ int   g_pos2[CE2];
__device__ int   g_bsum[64];
__device__ int   g_scan_done;

// ---------------------------------------------------------------------------
// merged histogram + ticket assignment (fill pass needs NO atomics)
// ---------------------------------------------------------------------------
__global__ void k_count(const int* __restrict__ d1, const int* __restrict__ d2,
                        int E1, int E2) {
    int i = blockIdx.x * blockDim.x + threadIdx.x;
    if (i < E1) {
        g_pos1[i] = atomicAdd(g_cnt1 + d1[i], 1);
    } else {
        int j = i - E1;
        if (j < E2) g_pos2[j] = atomicAdd(g_cnt2 + d2[j], 1);
    }
}

// ---------------------------------------------------------------------------
// Single-kernel segmented scan with device-wide spin barrier (44 blocks).
// Also re-zeroes cnt[] for the next graph replay.
// ---------------------------------------------------------------------------
__global__ void __launch_bounds__(1024) k_scan(int E1, int E2) {
    int b = blockIdx.x;
    int lay = (b >= NB1);
    int bb = lay ? b - NB1 : b;
    int n = lay ? CN2 : CN1;
    int segbase = lay ? NB1 : 0;
    int* cnt = lay ? g_cnt2 : g_cnt1;
    int* off = lay ? g_off2 : g_off1;
    __shared__ int ps[1024];
    __shared__ int add_s;
    int t = threadIdx.x;
    int i = bb * 1024 + t;
    int v = (i < n) ? cnt[i] : 0;
    ps[t] = v;
    __syncthreads();
    #pragma unroll
    for (int d = 1; d < 1024; d <<= 1) {
        int u = (t >= d) ? ps[t - d] : 0;
        __syncthreads();
        ps[t] += u;
        __syncthreads();
    }
    int local_ex = ps[t] - v;
    if (t == 0) g_bsum[b] = ps[1023];
    __threadfence();
    __syncthreads();
    if (t == 0) {
        atomicAdd(&g_scan_done, 1);
        while (*(volatile int*)&g_scan_done < NBT) { }
        __threadfence();
        int s = 0;
        for (int j = segbase; j < b; j++) s += g_bsum[j];
        add_s = s;
    }
    __syncthreads();
    int add = add_s;
    if (i < n) { off[i] = local_ex + add; cnt[i] = 0; }   // cnt reset for replay
    if (i == 0) off[n] = lay ? E2 : E1;
}

// atomic-free fill (ticket precomputed); also resets the scan barrier counter
__global__ void k_fill(const int* __restrict__ s1, const int* __restrict__ d1,
                       const int* __restrict__ s2, const int* __restrict__ d2,
                       int E1, int E2) {
    int i = blockIdx.x * blockDim.x + threadIdx.x;
    if (i == 0) g_scan_done = 0;          // safe: scan fully drained before fill
    if (i < E1) {
        int d = d1[i];
        g_csr1[g_off1[d] + g_pos1[i]] = s1[i];
    } else {
        int j = i - E1;
        if (j < E2) {
            int d = d2[j];
            g_csr2[g_off2[d] + g_pos2[j]] = s2[j];
        }
    }
}

// ---------------------------------------------------------------------------
// layer-1 gather-mean: warp per dst row, unroll 8
// ---------------------------------------------------------------------------
__global__ void __launch_bounds__(256) k_gather1(const float* __restrict__ x) {
    int w = (blockIdx.x * blockDim.x + threadIdx.x) >> 5;
    if (w >= CN1) return;
    int lane = threadIdx.x & 31;
    int e0 = g_off1[w], e1 = g_off1[w + 1];
    float4 acc = make_float4(0.f, 0.f, 0.f, 0.f);
    int i = e0;
    for (; i + 7 < e1; i += 8) {
        int sid[8];
        #pragma unroll
        for (int j = 0; j < 8; j++) sid[j] = g_csr1[i + j];
        float4 v[8];
        #pragma unroll
        for (int j = 0; j < 8; j++)
            v[j] = ((const float4*)(x + (size_t)sid[j] * CIN))[lane];
        #pragma unroll
        for (int j = 0; j < 8; j++) {
            acc.x += v[j].x; acc.y += v[j].y; acc.z += v[j].z; acc.w += v[j].w;
        }
    }
    for (; i + 3 < e1; i += 4) {
        int s0 = g_csr1[i], s1 = g_csr1[i + 1], s2 = g_csr1[i + 2], s3 = g_csr1[i + 3];
        float4 v0 = ((const float4*)(x + (size_t)s0 * CIN))[lane];
        float4 v1 = ((const float4*)(x + (size_t)s1 * CIN))[lane];
        float4 v2 = ((const float4*)(x + (size_t)s2 * CIN))[lane];
        float4 v3 = ((const float4*)(x + (size_t)s3 * CIN))[lane];
        acc.x += v0.x + v1.x + v2.x + v3.x;
        acc.y += v0.y + v1.y + v2.y + v3.y;
        acc.z += v0.z + v1.z + v2.z + v3.z;
        acc.w += v0.w + v1.w + v2.w + v3.w;
    }
    for (; i < e1; i++) {
        int s = g_csr1[i];
        float4 v = ((const float4*)(x + (size_t)s * CIN))[lane];
        acc.x += v.x; acc.y += v.y; acc.z += v.z; acc.w += v.w;
    }
    float id = 1.0f / fmaxf((float)(e1 - e0), 1.0f);
    acc.x *= id; acc.y *= id; acc.z *= id; acc.w *= id;
    ((float4*)(g_agg1 + (size_t)w * CIN))[lane] = acc;
}

// ---------------------------------------------------------------------------
// tf32 helpers — raw fp32 bits fed to mma.tf32 (HW truncates)
// ---------------------------------------------------------------------------
__device__ __forceinline__ void mma_tf32(float* c, const uint32_t* a, const uint32_t* b) {
    asm volatile(
        "mma.sync.aligned.m16n8k8.row.col.f32.tf32.tf32.f32 "
        "{%0,%1,%2,%3}, {%4,%5,%6,%7}, {%8,%9}, {%0,%1,%2,%3};"
        : "+f"(c[0]), "+f"(c[1]), "+f"(c[2]), "+f"(c[3])
        : "r"(a[0]), "r"(a[1]), "r"(a[2]), "r"(a[3]), "r"(b[0]), "r"(b[1]));
}

__device__ __forceinline__ uint32_t s2u(const void* p) {
    return (uint32_t)__cvta_generic_to_shared(p);
}

__device__ __forceinline__ void cp16(uint32_t dst, const void* src) {
    asm volatile("cp.async.cg.shared.global [%0], [%1], 16;"
                 :: "r"(dst), "l"(src));
}

// ---------------------------------------------------------------------------
// layer-1 GEMM (tf32, 3-stage cp.async pipeline, BM=64 x BN=256)
// ---------------------------------------------------------------------------
#define A_ST 1280
#define B_ST 4224
#define SMEM_GEMM1 ((3 * (A_ST + B_ST)) * 4)

__global__ void __launch_bounds__(256, 2) k_gemm1(const float* __restrict__ x,
                                                  const float* __restrict__ wl,
                                                  const float* __restrict__ wr,
                                                  const float* __restrict__ bias) {
    extern __shared__ float sm[];
    float* Abuf = sm;
    float* Bbuf = sm + 3 * A_ST;

    const int t = threadIdx.x;
    const int lane = t & 31, warp = t >> 5;
    const int warp_m = warp & 1;
    const int warp_n = warp >> 1;
    const int m0 = blockIdx.x * 64;
    const int fr = lane >> 2;
    const int fc = lane & 3;

    const int a_row = t >> 2,  a_kq = (t & 3) * 4;
    const int b_nq  = (t & 63) * 4;

    float acc[2][8][4] = {};

    auto issue = [&](int it, int st) {
        const int kk = (it & 7) * 16;
        const float* Abase = (it < 8) ? g_agg1 : x;
        const float* Bbase = (it < 8) ? wl : wr;
        float* As = Abuf + st * A_ST;
        float* Bs = Bbuf + st * B_ST;
        cp16(s2u(As + a_row * 20 + a_kq),
             Abase + (size_t)(m0 + a_row) * CIN + kk + a_kq);
        #pragma unroll
        for (int i = 0; i < 4; i++) {
            int krow = (t + i * 256) >> 6;
            cp16(s2u(Bs + krow * 264 + b_nq),
                 Bbase + (size_t)(kk + krow) * CHID + b_nq);
        }
    };

    issue(0, 0);
    asm volatile("cp.async.commit_group;");
    issue(1, 1);
    asm volatile("cp.async.commit_group;");

    int st = 0;
    for (int it = 0; it < 16; ++it) {
        asm volatile("cp.async.wait_group 1;");
        __syncthreads();
        if (it + 2 < 16) issue(it + 2, (st + 2) % 3);
        asm volatile("cp.async.commit_group;");

        const uint32_t* A = (const uint32_t*)(Abuf + st * A_ST);
        const uint32_t* B = (const uint32_t*)(Bbuf + st * B_ST);
        #pragma unroll
        for (int ks = 0; ks < 2; ks++) {
            const int kb = ks * 8;
            uint32_t a[2][4], b[8][2];
            #pragma unroll
            for (int mt = 0; mt < 2; mt++) {
                int mr = warp_m * 32 + mt * 16 + fr;
                a[mt][0] = A[mr * 20 + kb + fc];
                a[mt][1] = A[(mr + 8) * 20 + kb + fc];
                a[mt][2] = A[mr * 20 + kb + fc + 4];
                a[mt][3] = A[(mr + 8) * 20 + kb + fc + 4];
            }
            #pragma unroll
            for (int nt = 0; nt < 8; nt++) {
                int nc = warp_n * 64 + nt * 8 + fr;
                b[nt][0] = B[(kb + fc) * 264 + nc];
                b[nt][1] = B[(kb + fc + 4) * 264 + nc];
            }
            #pragma unroll
            for (int mt = 0; mt < 2; mt++)
                #pragma unroll
                for (int nt = 0; nt < 8; nt++)
                    mma_tf32(acc[mt][nt], a[mt], b[nt]);
        }
        st = (st + 1) % 3;
    }

    #pragma unroll
    for (int mt = 0; mt < 2; mt++) {
        int gm = m0 + warp_m * 32 + mt * 16 + fr;
        #pragma unroll
        for (int nt = 0; nt < 8; nt++) {
            int gn = warp_n * 64 + nt * 8 + (fc << 1);
            float b0 = bias[gn], b1 = bias[gn + 1];
            float2 v0 = make_float2(fmaxf(acc[mt][nt][0] + b0, 0.f),
                                    fmaxf(acc[mt][nt][1] + b1, 0.f));
            *(float2*)(g_h + (size_t)gm * CHID + gn) = v0;
            float2 v1 = make_float2(fmaxf(acc[mt][nt][2] + b0, 0.f),
                                    fmaxf(acc[mt][nt][3] + b1, 0.f));
            *(float2*)(g_h + (size_t)(gm + 8) * CHID + gn) = v1;
        }
    }
}

// ---------------------------------------------------------------------------
// FUSED layer-2: gather-mean + GEMM + log_softmax. Warp per dst row.
// Lane owns cols {2*lane, 2*lane+1} -> all weight/bias/output accesses are
// float2 (LDG.64/STG.64), halving load-issue count vs the {lane, lane+32} map.
// ---------------------------------------------------------------------------
__global__ void __launch_bounds__(256) k_gemm2(const float* __restrict__ wl,
                                               const float* __restrict__ wr,
                                               const float* __restrict__ bias,
                                               float* __restrict__ out) {
    __shared__ float As[8][512];
    int warp = threadIdx.x >> 5, lane = threadIdx.x & 31;
    int m = blockIdx.x * 8 + warp;
    if (m >= CN2) return;

    // inline gather-mean of neighbor h rows
    {
        int e0 = g_off2[m], e1 = g_off2[m + 1];
        float4 a0 = make_float4(0.f, 0.f, 0.f, 0.f);
        float4 a1 = a0;
        int i = e0;
        for (; i + 1 < e1; i += 2) {
            const float4* p0 = (const float4*)(g_h + (size_t)g_csr2[i] * CHID);
            const float4* p1 = (const float4*)(g_h + (size_t)g_csr2[i + 1] * CHID);
            float4 u0 = p0[lane], u1 = p0[lane + 32];
            float4 v0 = p1[lane], v1 = p1[lane + 32];
            a0.x += u0.x + v0.x; a0.y += u0.y + v0.y;
            a0.z += u0.z + v0.z; a0.w += u0.w + v0.w;
            a1.x += u1.x + v1.x; a1.y += u1.y + v1.y;
            a1.z += u1.z + v1.z; a1.w += u1.w + v1.w;
        }
        for (; i < e1; i++) {
            const float4* p = (const float4*)(g_h + (size_t)g_csr2[i] * CHID);
            float4 u0 = p[lane], u1 = p[lane + 32];
            a0.x += u0.x; a0.y += u0.y; a0.z += u0.z; a0.w += u0.w;
            a1.x += u1.x; a1.y += u1.y; a1.z += u1.z; a1.w += u1.w;
        }
        float id = 1.0f / fmaxf((float)(e1 - e0), 1.0f);
        a0.x *= id; a0.y *= id; a0.z *= id; a0.w *= id;
        a1.x *= id; a1.y *= id; a1.z *= id; a1.w *= id;
        ((float4*)As[warp])[lane] = a0;
        ((float4*)As[warp])[lane + 32] = a1;
    }
    #pragma unroll
    for (int i = 0; i < 8; i++)
        As[warp][CHID + lane + 32 * i] = g_h[(size_t)m * CHID + lane + 32 * i];
    __syncwarp();

    const float2* wlv = (const float2*)wl;   // wl[k*64 + 2*lane] = wlv[k*32+lane]
    const float2* wrv = (const float2*)wr;
    float acc0 = 0.f, acc1 = 0.f;
    const float* A = As[warp];
    #pragma unroll 8
    for (int k = 0; k < CHID; k++) {
        float a = A[k];
        float2 w = wlv[k * 32 + lane];
        acc0 += a * w.x;
        acc1 += a * w.y;
    }
    #pragma unroll 8
    for (int k = 0; k < CHID; k++) {
        float a = A[CHID + k];
        float2 w = wrv[k * 32 + lane];
        acc0 += a * w.x;
        acc1 += a * w.y;
    }
    float2 bv = ((const float2*)bias)[lane];
    acc0 += bv.x;
    acc1 += bv.y;

    float mx = fmaxf(acc0, acc1);
    #pragma unroll
    for (int o = 16; o > 0; o >>= 1) mx = fmaxf(mx, __shfl_xor_sync(0xFFFFFFFFu, mx, o));
    float s = expf(acc0 - mx) + expf(acc1 - mx);
    #pragma unroll
    for (int o = 16; o > 0; o >>= 1) s += __shfl_xor_sync(0xFFFFFFFFu, s, o);
    float lse = mx + logf(s);
    ((float2*)(out + (size_t)m * COUT))[lane] = make_float2(acc0 - lse, acc1 - lse);
}

// ---------------------------------------------------------------------------
extern "C" void kernel_launch(void* const* d_in, const int* in_sizes, int n_in,
                              void* d_out, int out_size) {
    const float* x    = (const float*)d_in[0];
    const int*   src1 = (const int*)d_in[1];
    const int*   dst1 = (const int*)d_in[2];
    const int*   src2 = (const int*)d_in[3];
    const int*   dst2 = (const int*)d_in[4];
    const float* wl1  = (const float*)d_in[5];
    const float* bl1  = (const float*)d_in[6];
    const float* wr1  = (const float*)d_in[7];
    const float* wl2  = (const float*)d_in[8];
    const float* bl2  = (const float*)d_in[9];
    const float* wr2  = (const float*)d_in[10];
    int E1 = in_sizes[1];
    int E2 = in_sizes[3];

    cudaFuncSetAttribute(k_gemm1, cudaFuncAttributeMaxDynamicSharedMemorySize,
                         SMEM_GEMM1);

    k_count<<<(E1 + E2 + 255) / 256, 256>>>(dst1, dst2, E1, E2);
    k_scan<<<NBT, 1024>>>(E1, E2);
    k_fill<<<(E1 + E2 + 255) / 256, 256>>>(src1, dst1, src2, dst2, E1, E2);
    k_gather1<<<(CN1 * 32 + 255) / 256, 256>>>(x);
    k_gemm1<<<CN1 / 64, 256, SMEM_GEMM1>>>(x, wl1, wr1, bl1);
    k_gemm2<<<(CN2 + 7) / 8, 256>>>(wl2, wr2, bl2, (float*)d_out);
}